// round 16
// baseline (speedup 1.0000x reference)
#include <cuda_runtime.h>
#include <stdint.h>
#include <math.h>

#define TT 2048
#define BB 16
#define NN 2048
#define HH 1024
#define SPL 37       // 37*16 = 592 CTAs = exactly 2 waves of 296 slots
#define CHUNK 56     // 37*56 = 2072 >= 2048; split 36 has 32 real timesteps
#define THR 256      // k_main threads (8 warps), 2 CTAs/SM

// scratch (device globals: no allocation allowed in kernel_launch)
__device__ float g_dfpart[2*BB*NN];   // split-K halves of dec_fea (+bias in half 0)
__device__ float g_scores[TT*BB];     // only unmasked entries written
__device__ float g_m[BB*SPL];
__device__ float g_z[BB*SPL];
__device__ float g_acc[BB*SPL*NN];    // ~4.8 MB
__device__ unsigned char g_mask8[TT*BB];

// single-MUFU tanh (sm_75+), abs err ~2e-4 — fine vs 1e-3 threshold
__device__ __forceinline__ float tanhfast(float x){
    float y;
    asm("tanh.approx.f32 %0, %1;" : "=f"(y) : "f"(x));
    return y;
}

__device__ __forceinline__ float4 ldcs4(const float4* p){
    float4 r;
    asm("ld.global.cs.v4.f32 {%0,%1,%2,%3}, [%4];"
        : "=f"(r.x), "=f"(r.y), "=f"(r.z), "=f"(r.w) : "l"(p));
    return r;
}

// ---------------------------------------------------------------------------
// Kernel 1: split-K dec_fea (R15 version, measured 10.2 us).
// 512 CTAs = 256 row-groups x 2 K-halves; 128 thr. CTA stages its 32 KB dec
// K-half for all 16 batches; each warp owns 2 rows over 512 K. Halves write
// disjoint g_dfpart arrays (deterministic); k_main sums them.
// Also converts the padding mask to uint8 (dtype auto-detected).
// ---------------------------------------------------------------------------
__global__ __launch_bounds__(128) void k_decfea(
    const float* __restrict__ dec,
    const float* __restrict__ Wd,
    const float* __restrict__ bd,
    const unsigned char* __restrict__ mraw){
    __shared__ __align__(16) float sdec[BB*512];   // 32 KB: one K-half, 16 batches
    // ---- mask conversion ----
    {
        const unsigned int* w = (const unsigned int*)mraw;
        int is_word = 1;   // int32 (0/1) or float32 (0.0/1.0) storage
        #pragma unroll
        for (int i = 0; i < 32; ++i){
            unsigned int x = w[i];
            if (x != 0u && x != 1u && x != 0x3F800000u) is_word = 0;
        }
        int idx = blockIdx.x*128 + threadIdx.x;
        if (idx < TT*BB){
            unsigned char mv = is_word ? (unsigned char)(w[idx] != 0u)
                                       : (unsigned char)(mraw[idx] != 0);
            g_mask8[idx] = mv;
        }
    }

    int tid  = threadIdx.x;
    int wid  = tid >> 5, lane = tid & 31;
    int group = blockIdx.x >> 1;      // 0..255
    int half  = blockIdx.x & 1;       // K-half
    int nbase = group*8 + wid*2;      // this warp's row pair

    const float4* wp0 = (const float4*)(Wd + (size_t)(nbase+0)*HH);
    const float4* wp1 = (const float4*)(Wd + (size_t)(nbase+1)*HH);

    float4 wv0[4], wv1[4];
    #pragma unroll
    for (int ch = 0; ch < 4; ++ch){
        wv0[ch] = wp0[half*128 + ch*32 + lane];
        wv1[ch] = wp1[half*128 + ch*32 + lane];
    }

    // stage this K-half of dec: 16 b x 128 float4 / 128 thr
    {
        const float4* dg = (const float4*)dec;
        float4* sg = (float4*)sdec;
        #pragma unroll
        for (int j = 0; j < 16; ++j){
            int f = tid + j*128;
            int b = f >> 7, k4 = f & 127;
            sg[f] = dg[b*256 + half*128 + k4];
        }
    }
    __syncthreads();

    const float4* sd = (const float4*)sdec;
    float acc0[BB], acc1[BB];
    #pragma unroll
    for (int b = 0; b < BB; ++b){ acc0[b] = 0.f; acc1[b] = 0.f; }

    #pragma unroll
    for (int ch = 0; ch < 4; ++ch){
        #pragma unroll
        for (int b = 0; b < BB; ++b){
            float4 d = sd[b*128 + ch*32 + lane];
            acc0[b] += wv0[ch].x*d.x + wv0[ch].y*d.y + wv0[ch].z*d.z + wv0[ch].w*d.w;
            acc1[b] += wv1[ch].x*d.x + wv1[ch].y*d.y + wv1[ch].z*d.z + wv1[ch].w*d.w;
        }
    }
    float bias0 = half ? 0.f : bd[nbase];
    float bias1 = half ? 0.f : bd[nbase+1];
    float* outp = g_dfpart + half*(BB*NN);
    #pragma unroll
    for (int b = 0; b < BB; ++b){
        float s0 = acc0[b], s1 = acc1[b];
        #pragma unroll
        for (int off = 16; off; off >>= 1){
            s0 += __shfl_xor_sync(0xffffffffu, s0, off);
            s1 += __shfl_xor_sync(0xffffffffu, s1, off);
        }
        if (lane == 0){
            float2 o = make_float2(s0 + bias0, s1 + bias1);
            *(float2*)(outp + b*NN + nbase) = o;    // nbase even -> 8B aligned
        }
    }
}

// ---------------------------------------------------------------------------
// Kernel 2: fused scores + online softmax + context partial, mask-compacted
// (R11/R14 static body). grid (SPL=37, BB) = 592 CTAs = exactly 2 full waves.
// 256 thr; 2 CTAs/SM; 4-row register prefetch. Out-of-range t (split 36)
// treated as masked.
// ---------------------------------------------------------------------------
__global__ __launch_bounds__(THR, 2) void k_main(
    const float* __restrict__ enc,
    const float* __restrict__ cov,
    const float* __restrict__ wc,
    const float* __restrict__ v)
{
    __shared__ float scov[CHUNK];
    __shared__ unsigned char smask[CHUNK];
    __shared__ short slist[CHUNK];    // compacted local t-indices (unmasked)
    __shared__ int   scnt;
    __shared__ float sred[8][5];      // [warp][score], padded
    __shared__ float sbc[4];
    int tid  = threadIdx.x;
    int wid  = tid >> 5, lane = tid & 31;
    int sp = blockIdx.x, b = blockIdx.y;
    int t0 = sp * CHUNK;

    if (tid < CHUNK){
        int t = t0 + tid;
        if (t < TT){
            scov[tid]  = cov[t*BB + b];
            smask[tid] = g_mask8[t*BB + b];
        } else {
            scov[tid]  = 0.f;
            smask[tid] = 1;            // out-of-range => masked
        }
    }
    int n0 = tid * 8;
    // dec_fea = sum of split-K halves
    float4 dfa0 = *(const float4*)(g_dfpart + b*NN + n0);
    float4 dfa1 = *(const float4*)(g_dfpart + b*NN + n0 + 4);
    float4 dfb0 = *(const float4*)(g_dfpart + BB*NN + b*NN + n0);
    float4 dfb1 = *(const float4*)(g_dfpart + BB*NN + b*NN + n0 + 4);
    float4 df0 = make_float4(dfa0.x+dfb0.x, dfa0.y+dfb0.y, dfa0.z+dfb0.z, dfa0.w+dfb0.w);
    float4 df1 = make_float4(dfa1.x+dfb1.x, dfa1.y+dfb1.y, dfa1.z+dfb1.z, dfa1.w+dfb1.w);
    float4 w0  = *(const float4*)(wc + n0);
    float4 w1  = *(const float4*)(wc + n0 + 4);
    float4 v0  = *(const float4*)(v + n0);
    float4 v1  = *(const float4*)(v + n0 + 4);
    __syncthreads();

    // ---- build compacted unmasked list (warp 0, ballot + popc) ----
    if (tid < 32){
        unsigned mk0 = __ballot_sync(0xffffffffu, smask[tid] == 0);
        int idx1 = 32 + tid;
        bool ok1 = (idx1 < CHUNK) && (smask[idx1] == 0);
        unsigned mk1 = __ballot_sync(0xffffffffu, ok1);
        int c0 = __popc(mk0);
        int cnt = c0 + __popc(mk1);
        if (smask[tid] == 0)
            slist[__popc(mk0 & ((1u << tid) - 1u))] = (short)tid;
        if (ok1)
            slist[c0 + __popc(mk1 & ((1u << tid) - 1u))] = (short)idx1;
        __syncwarp();
        if (tid == 0){
            scnt = cnt;
            int padded = (cnt + 3) & ~3;
            for (int i = cnt; i < padded; ++i) slist[i] = slist[cnt > 0 ? cnt-1 : 0];
        }
    }
    __syncthreads();
    int cnt = scnt;

    float m = -INFINITY, Z = 0.f;
    float4 A0 = make_float4(0.f,0.f,0.f,0.f);
    float4 A1 = make_float4(0.f,0.f,0.f,0.f);

    if (cnt > 0){
        int nb = (cnt + 3) >> 2;
        // prefetch batch 0 (4 compacted rows)
        int li[4];
        float4 c0[4], c1[4];
        #pragma unroll
        for (int i = 0; i < 4; ++i){
            li[i] = slist[i];
            const float4* rp = (const float4*)(enc + ((size_t)(t0+li[i])*BB + b)*NN + n0);
            c0[i] = ldcs4(rp); c1[i] = ldcs4(rp + 1);
        }
        for (int it = 0; it < nb; ++it){
            bool havenext = (it + 1 < nb);
            int ni[4];
            float4 x0[4], x1[4];
            if (havenext){
                #pragma unroll
                for (int i = 0; i < 4; ++i){
                    ni[i] = slist[(it+1)*4 + i];
                    const float4* rp = (const float4*)(enc + ((size_t)(t0+ni[i])*BB + b)*NN + n0);
                    x0[i] = ldcs4(rp); x1[i] = ldcs4(rp + 1);
                }
            }
            float part[4];
            #pragma unroll
            for (int i = 0; i < 4; ++i){
                float cv = scov[li[i]];
                float p;
                p  = tanhfast(fmaf(cv, w0.x, c0[i].x + df0.x)) * v0.x;
                p += tanhfast(fmaf(cv, w0.y, c0[i].y + df0.y)) * v0.y;
                p += tanhfast(fmaf(cv, w0.z, c0[i].z + df0.z)) * v0.z;
                p += tanhfast(fmaf(cv, w0.w, c0[i].w + df0.w)) * v0.w;
                p += tanhfast(fmaf(cv, w1.x, c1[i].x + df1.x)) * v1.x;
                p += tanhfast(fmaf(cv, w1.y, c1[i].y + df1.y)) * v1.y;
                p += tanhfast(fmaf(cv, w1.z, c1[i].z + df1.z)) * v1.z;
                p += tanhfast(fmaf(cv, w1.w, c1[i].w + df1.w)) * v1.w;
                part[i] = p;
            }
            // stage 1: warp reduce 4 partials
            #pragma unroll
            for (int i = 0; i < 4; ++i)
                #pragma unroll
                for (int off = 16; off; off >>= 1)
                    part[i] += __shfl_xor_sync(0xffffffffu, part[i], off);
            if (lane == 0){
                #pragma unroll
                for (int i = 0; i < 4; ++i) sred[wid][i] = part[i];
            }
            __syncthreads();
            // stage 2: 32 threads, 8-lane groups, one score each
            if (tid < 32){
                int s  = tid >> 3;
                int ww = tid & 7;
                float val = sred[ww][s];
                val += __shfl_xor_sync(0xffffffffu, val, 1);
                val += __shfl_xor_sync(0xffffffffu, val, 2);
                val += __shfl_xor_sync(0xffffffffu, val, 4);
                if (ww == 0) sbc[s] = val;
            }
            __syncthreads();
            // scores for valid (non-pad) entries only
            if (tid < 4){
                int idx = it*4 + tid;
                if (idx < cnt) g_scores[(t0 + slist[idx])*BB + b] = sbc[tid];
            }
            float s[4];
            #pragma unroll
            for (int i = 0; i < 4; ++i)
                s[i] = (it*4 + i < cnt) ? sbc[i] : -INFINITY;

            // online softmax update (pads have s=-inf -> p=0)
            float m2 = m;
            #pragma unroll
            for (int i = 0; i < 4; ++i) m2 = fmaxf(m2, s[i]);
            float sc = __expf(m - m2);             // m==-inf -> 0 (A still 0)
            float p[4];
            #pragma unroll
            for (int i = 0; i < 4; ++i) p[i] = __expf(s[i] - m2);
            Z = Z*sc + (p[0]+p[1]) + (p[2]+p[3]);
            float ax = A0.x*sc, ay = A0.y*sc, az = A0.z*sc, aw = A0.w*sc;
            float bx = A1.x*sc, by = A1.y*sc, bz = A1.z*sc, bw = A1.w*sc;
            #pragma unroll
            for (int i = 0; i < 4; ++i){
                ax = fmaf(p[i], c0[i].x, ax); ay = fmaf(p[i], c0[i].y, ay);
                az = fmaf(p[i], c0[i].z, az); aw = fmaf(p[i], c0[i].w, aw);
                bx = fmaf(p[i], c1[i].x, bx); by = fmaf(p[i], c1[i].y, by);
                bz = fmaf(p[i], c1[i].z, bz); bw = fmaf(p[i], c1[i].w, bw);
            }
            A0 = make_float4(ax, ay, az, aw);
            A1 = make_float4(bx, by, bz, bw);
            m = m2;

            if (havenext){
                #pragma unroll
                for (int i = 0; i < 4; ++i){
                    li[i] = ni[i]; c0[i] = x0[i]; c1[i] = x1[i];
                }
            }
        }
    }
    if (tid == 0){
        g_m[b*SPL + sp] = m;
        g_z[b*SPL + sp] = Z;
    }
    float4* op = (float4*)(g_acc + (size_t)(b*SPL + sp)*NN + n0);
    op[0] = A0; op[1] = A1;
}

// ---------------------------------------------------------------------------
// Kernel 3: combine (37 splits). blocks 0..63: context c[b, n-quarter].
// blocks 64..191: attn + coverage, float4 flat-indexed; masked -> attn 0.
// ---------------------------------------------------------------------------
__global__ void k_combine(const float* __restrict__ cov,
                          float* __restrict__ out){
    int tid = threadIdx.x;
    if (blockIdx.x < 4*BB){
        int b = blockIdx.x >> 2, q = blockIdx.x & 3;
        __shared__ float sw[SPL];
        if (tid < 32){
            // lane owns splits lane and lane+32 (latter only if < SPL)
            float m0 = g_m[b*SPL + tid], z0 = g_z[b*SPL + tid];
            bool has1 = (tid + 32) < SPL;
            float m1 = has1 ? g_m[b*SPL + tid + 32] : -INFINITY;
            float z1 = has1 ? g_z[b*SPL + tid + 32] : 0.f;
            float M = fmaxf(m0, m1);
            #pragma unroll
            for (int off = 16; off; off >>= 1)
                M = fmaxf(M, __shfl_xor_sync(0xffffffffu, M, off));
            float Zs = z0*__expf(m0 - M) + z1*__expf(m1 - M);
            #pragma unroll
            for (int off = 16; off; off >>= 1)
                Zs += __shfl_xor_sync(0xffffffffu, Zs, off);
            float inv = 1.0f / Zs;
            sw[tid] = __expf(m0 - M) * inv;
            if (has1) sw[tid + 32] = __expf(m1 - M) * inv;
        }
        __syncthreads();
        if (tid < 128){
            int n0 = q*512 + tid*4;
            float4 r = make_float4(0.f,0.f,0.f,0.f);
            #pragma unroll
            for (int s = 0; s < SPL; ++s){
                float4 x = *(const float4*)(g_acc + (size_t)(b*SPL + s)*NN + n0);
                float wgt = sw[s];
                r.x = fmaf(wgt, x.x, r.x); r.y = fmaf(wgt, x.y, r.y);
                r.z = fmaf(wgt, x.z, r.z); r.w = fmaf(wgt, x.w, r.w);
            }
            *(float4*)(out + b*NN + n0) = r;
        }
    } else {
        __shared__ float sM[BB], sInv[BB];
        if (tid < BB){
            int b = tid;
            float M = -INFINITY;
            #pragma unroll
            for (int s = 0; s < SPL; ++s) M = fmaxf(M, g_m[b*SPL + s]);
            float Zs = 0.f;
            #pragma unroll
            for (int s = 0; s < SPL; ++s) Zs += g_z[b*SPL + s] * __expf(g_m[b*SPL + s] - M);
            sM[b] = M; sInv[b] = 1.0f / Zs;
        }
        __syncthreads();
        int q = (blockIdx.x - 4*BB) * 256 + tid;    // 128 blocks -> 8192 quads
        int flat = q * 4;
        if (q < (TT*BB)/4){
            float4 sc = *(const float4*)(g_scores + flat);
            float4 cv = *(const float4*)(cov + flat);
            uchar4 mk = *(const uchar4*)(g_mask8 + flat);
            int b0 = flat & (BB-1);
            float4 a;
            a.x = mk.x ? 0.f : __expf(sc.x - sM[b0  ]) * sInv[b0  ];
            a.y = mk.y ? 0.f : __expf(sc.y - sM[b0+1]) * sInv[b0+1];
            a.z = mk.z ? 0.f : __expf(sc.z - sM[b0+2]) * sInv[b0+2];
            a.w = mk.w ? 0.f : __expf(sc.w - sM[b0+3]) * sInv[b0+3];
            *(float4*)(out + BB*NN + flat) = a;
            float4 cg = make_float4(cv.x + a.x, cv.y + a.y, cv.z + a.z, cv.w + a.w);
            *(float4*)(out + BB*NN + TT*BB + flat) = cg;
        }
    }
}

// ---------------------------------------------------------------------------
extern "C" void kernel_launch(void* const* d_in, const int* in_sizes, int n_in,
                              void* d_out, int out_size){
    const float*         dec  = (const float*)d_in[0];          // [B,H]
    const float*         enc  = (const float*)d_in[1];          // [T,B,N]
    const unsigned char* mask = (const unsigned char*)d_in[2];  // [T,B] (dtype auto-detected)
    const float*         cov  = (const float*)d_in[3];          // [T,B]
    const float*         Wd   = (const float*)d_in[4];          // [N,H]
    const float*         bd   = (const float*)d_in[5];          // [N]
    const float*         wc   = (const float*)d_in[6];          // [N]
    const float*         v    = (const float*)d_in[7];          // [N]
    float* out = (float*)d_out;  // c[B,N] | attn[T,B] | coverage_out[T,B]

    k_decfea<<<512, 128>>>(dec, Wd, bd, mask);
    k_main<<<dim3(SPL, BB), THR>>>(enc, cov, wc, v);
    k_combine<<<4*BB + (TT*BB/4 + 255)/256, 256>>>(cov, out);
}

// round 17
// speedup vs baseline: 1.3934x; 1.3934x over previous
#include <cuda_runtime.h>
#include <stdint.h>
#include <math.h>

#define TT 2048
#define BB 16
#define NN 2048
#define HH 1024
#define SPL 32
#define CHUNK 64     // timesteps per tile before masking (~32 survive)
#define THR 256      // k_main threads (8 warps), 2 CTAs/SM

// scratch (device globals: no allocation allowed in kernel_launch)
__device__ float g_dfpart[2*BB*NN];   // split-K halves of dec_fea (+bias in half 0)
__device__ float g_scores[TT*BB];     // only unmasked entries written
__device__ float g_m[BB*SPL];
__device__ float g_z[BB*SPL];
__device__ float g_acc[BB*SPL*NN];    // 4 MB
__device__ unsigned char g_mask8[TT*BB];

// single-MUFU tanh (sm_75+), abs err ~2e-4 — fine vs 1e-3 threshold
__device__ __forceinline__ float tanhfast(float x){
    float y;
    asm("tanh.approx.f32 %0, %1;" : "=f"(y) : "f"(x));
    return y;
}

__device__ __forceinline__ float4 ldcs4(const float4* p){
    float4 r;
    asm("ld.global.cs.v4.f32 {%0,%1,%2,%3}, [%4];"
        : "=f"(r.x), "=f"(r.y), "=f"(r.z), "=f"(r.w) : "l"(p));
    return r;
}

// ---------------------------------------------------------------------------
// Kernel 1: split-K dec_fea (R15 version, measured 10.2 us on a clean run).
// 512 CTAs = 256 row-groups x 2 K-halves; 128 thr. CTA stages its 32 KB dec
// K-half for all 16 batches; each warp owns 2 rows over 512 K. Halves write
// disjoint g_dfpart arrays (deterministic); k_main sums them.
// Also converts the padding mask to uint8 (dtype auto-detected).
// ---------------------------------------------------------------------------
__global__ __launch_bounds__(128) void k_decfea(
    const float* __restrict__ dec,
    const float* __restrict__ Wd,
    const float* __restrict__ bd,
    const unsigned char* __restrict__ mraw){
    __shared__ __align__(16) float sdec[BB*512];   // 32 KB: one K-half, 16 batches
    // ---- mask conversion ----
    {
        const unsigned int* w = (const unsigned int*)mraw;
        int is_word = 1;   // int32 (0/1) or float32 (0.0/1.0) storage
        #pragma unroll
        for (int i = 0; i < 32; ++i){
            unsigned int x = w[i];
            if (x != 0u && x != 1u && x != 0x3F800000u) is_word = 0;
        }
        int idx = blockIdx.x*128 + threadIdx.x;
        if (idx < TT*BB){
            unsigned char mv = is_word ? (unsigned char)(w[idx] != 0u)
                                       : (unsigned char)(mraw[idx] != 0);
            g_mask8[idx] = mv;
        }
    }

    int tid  = threadIdx.x;
    int wid  = tid >> 5, lane = tid & 31;
    int group = blockIdx.x >> 1;      // 0..255
    int half  = blockIdx.x & 1;       // K-half
    int nbase = group*8 + wid*2;      // this warp's row pair

    const float4* wp0 = (const float4*)(Wd + (size_t)(nbase+0)*HH);
    const float4* wp1 = (const float4*)(Wd + (size_t)(nbase+1)*HH);

    float4 wv0[4], wv1[4];
    #pragma unroll
    for (int ch = 0; ch < 4; ++ch){
        wv0[ch] = wp0[half*128 + ch*32 + lane];
        wv1[ch] = wp1[half*128 + ch*32 + lane];
    }

    // stage this K-half of dec: 16 b x 128 float4 / 128 thr
    {
        const float4* dg = (const float4*)dec;
        float4* sg = (float4*)sdec;
        #pragma unroll
        for (int j = 0; j < 16; ++j){
            int f = tid + j*128;
            int b = f >> 7, k4 = f & 127;
            sg[f] = dg[b*256 + half*128 + k4];
        }
    }
    __syncthreads();

    const float4* sd = (const float4*)sdec;
    float acc0[BB], acc1[BB];
    #pragma unroll
    for (int b = 0; b < BB; ++b){ acc0[b] = 0.f; acc1[b] = 0.f; }

    #pragma unroll
    for (int ch = 0; ch < 4; ++ch){
        #pragma unroll
        for (int b = 0; b < BB; ++b){
            float4 d = sd[b*128 + ch*32 + lane];
            acc0[b] += wv0[ch].x*d.x + wv0[ch].y*d.y + wv0[ch].z*d.z + wv0[ch].w*d.w;
            acc1[b] += wv1[ch].x*d.x + wv1[ch].y*d.y + wv1[ch].z*d.z + wv1[ch].w*d.w;
        }
    }
    float bias0 = half ? 0.f : bd[nbase];
    float bias1 = half ? 0.f : bd[nbase+1];
    float* outp = g_dfpart + half*(BB*NN);
    #pragma unroll
    for (int b = 0; b < BB; ++b){
        float s0 = acc0[b], s1 = acc1[b];
        #pragma unroll
        for (int off = 16; off; off >>= 1){
            s0 += __shfl_xor_sync(0xffffffffu, s0, off);
            s1 += __shfl_xor_sync(0xffffffffu, s1, off);
        }
        if (lane == 0){
            float2 o = make_float2(s0 + bias0, s1 + bias1);
            *(float2*)(outp + b*NN + nbase) = o;    // nbase even -> 8B aligned
        }
    }
}

// ---------------------------------------------------------------------------
// Kernel 2: fused scores + online softmax + context partial, mask-compacted
// (R14 static body — measured k_main ~31 us, best). grid (SPL=32, BB) = 512
// CTAs; 256 thr; 2 CTAs/SM; 4-row register prefetch.
// ---------------------------------------------------------------------------
__global__ __launch_bounds__(THR, 2) void k_main(
    const float* __restrict__ enc,
    const float* __restrict__ cov,
    const float* __restrict__ wc,
    const float* __restrict__ v)
{
    __shared__ float scov[CHUNK];
    __shared__ unsigned char smask[CHUNK];
    __shared__ short slist[CHUNK];    // compacted local t-indices (unmasked)
    __shared__ int   scnt;
    __shared__ float sred[8][5];      // [warp][score], padded
    __shared__ float sbc[4];
    int tid  = threadIdx.x;
    int wid  = tid >> 5, lane = tid & 31;
    int sp = blockIdx.x, b = blockIdx.y;
    int t0 = sp * CHUNK;

    if (tid < CHUNK){
        scov[tid]  = cov[(t0 + tid)*BB + b];
        smask[tid] = g_mask8[(t0 + tid)*BB + b];
    }
    int n0 = tid * 8;
    // dec_fea = sum of split-K halves
    float4 dfa0 = *(const float4*)(g_dfpart + b*NN + n0);
    float4 dfa1 = *(const float4*)(g_dfpart + b*NN + n0 + 4);
    float4 dfb0 = *(const float4*)(g_dfpart + BB*NN + b*NN + n0);
    float4 dfb1 = *(const float4*)(g_dfpart + BB*NN + b*NN + n0 + 4);
    float4 df0 = make_float4(dfa0.x+dfb0.x, dfa0.y+dfb0.y, dfa0.z+dfb0.z, dfa0.w+dfb0.w);
    float4 df1 = make_float4(dfa1.x+dfb1.x, dfa1.y+dfb1.y, dfa1.z+dfb1.z, dfa1.w+dfb1.w);
    float4 w0  = *(const float4*)(wc + n0);
    float4 w1  = *(const float4*)(wc + n0 + 4);
    float4 v0  = *(const float4*)(v + n0);
    float4 v1  = *(const float4*)(v + n0 + 4);
    __syncthreads();

    // ---- build compacted unmasked list (warp 0, ballot + popc) ----
    if (tid < 32){
        unsigned mk0 = __ballot_sync(0xffffffffu, smask[tid] == 0);
        unsigned mk1 = __ballot_sync(0xffffffffu, smask[32 + tid] == 0);
        int c0 = __popc(mk0);
        int cnt = c0 + __popc(mk1);
        if (smask[tid] == 0)
            slist[__popc(mk0 & ((1u << tid) - 1u))] = (short)tid;
        if (smask[32 + tid] == 0)
            slist[c0 + __popc(mk1 & ((1u << tid) - 1u))] = (short)(32 + tid);
        __syncwarp();
        if (tid == 0){
            scnt = cnt;
            int padded = (cnt + 3) & ~3;
            for (int i = cnt; i < padded; ++i) slist[i] = slist[cnt > 0 ? cnt-1 : 0];
        }
    }
    __syncthreads();
    int cnt = scnt;

    float m = -INFINITY, Z = 0.f;
    float4 A0 = make_float4(0.f,0.f,0.f,0.f);
    float4 A1 = make_float4(0.f,0.f,0.f,0.f);

    if (cnt > 0){
        int nb = (cnt + 3) >> 2;
        // prefetch batch 0 (4 compacted rows)
        int li[4];
        float4 c0[4], c1[4];
        #pragma unroll
        for (int i = 0; i < 4; ++i){
            li[i] = slist[i];
            const float4* rp = (const float4*)(enc + ((size_t)(t0+li[i])*BB + b)*NN + n0);
            c0[i] = ldcs4(rp); c1[i] = ldcs4(rp + 1);
        }
        for (int it = 0; it < nb; ++it){
            bool havenext = (it + 1 < nb);
            int ni[4];
            float4 x0[4], x1[4];
            if (havenext){
                #pragma unroll
                for (int i = 0; i < 4; ++i){
                    ni[i] = slist[(it+1)*4 + i];
                    const float4* rp = (const float4*)(enc + ((size_t)(t0+ni[i])*BB + b)*NN + n0);
                    x0[i] = ldcs4(rp); x1[i] = ldcs4(rp + 1);
                }
            }
            float part[4];
            #pragma unroll
            for (int i = 0; i < 4; ++i){
                float cv = scov[li[i]];
                float p;
                p  = tanhfast(fmaf(cv, w0.x, c0[i].x + df0.x)) * v0.x;
                p += tanhfast(fmaf(cv, w0.y, c0[i].y + df0.y)) * v0.y;
                p += tanhfast(fmaf(cv, w0.z, c0[i].z + df0.z)) * v0.z;
                p += tanhfast(fmaf(cv, w0.w, c0[i].w + df0.w)) * v0.w;
                p += tanhfast(fmaf(cv, w1.x, c1[i].x + df1.x)) * v1.x;
                p += tanhfast(fmaf(cv, w1.y, c1[i].y + df1.y)) * v1.y;
                p += tanhfast(fmaf(cv, w1.z, c1[i].z + df1.z)) * v1.z;
                p += tanhfast(fmaf(cv, w1.w, c1[i].w + df1.w)) * v1.w;
                part[i] = p;
            }
            // stage 1: warp reduce 4 partials
            #pragma unroll
            for (int i = 0; i < 4; ++i)
                #pragma unroll
                for (int off = 16; off; off >>= 1)
                    part[i] += __shfl_xor_sync(0xffffffffu, part[i], off);
            if (lane == 0){
                #pragma unroll
                for (int i = 0; i < 4; ++i) sred[wid][i] = part[i];
            }
            __syncthreads();
            // stage 2: 32 threads, 8-lane groups, one score each
            if (tid < 32){
                int s  = tid >> 3;
                int ww = tid & 7;
                float val = sred[ww][s];
                val += __shfl_xor_sync(0xffffffffu, val, 1);
                val += __shfl_xor_sync(0xffffffffu, val, 2);
                val += __shfl_xor_sync(0xffffffffu, val, 4);
                if (ww == 0) sbc[s] = val;
            }
            __syncthreads();
            // scores for valid (non-pad) entries only
            if (tid < 4){
                int idx = it*4 + tid;
                if (idx < cnt) g_scores[(t0 + slist[idx])*BB + b] = sbc[tid];
            }
            float s[4];
            #pragma unroll
            for (int i = 0; i < 4; ++i)
                s[i] = (it*4 + i < cnt) ? sbc[i] : -INFINITY;

            // online softmax update (pads have s=-inf -> p=0)
            float m2 = m;
            #pragma unroll
            for (int i = 0; i < 4; ++i) m2 = fmaxf(m2, s[i]);
            float sc = __expf(m - m2);             // m==-inf -> 0 (A still 0)
            float p[4];
            #pragma unroll
            for (int i = 0; i < 4; ++i) p[i] = __expf(s[i] - m2);
            Z = Z*sc + (p[0]+p[1]) + (p[2]+p[3]);
            float ax = A0.x*sc, ay = A0.y*sc, az = A0.z*sc, aw = A0.w*sc;
            float bx = A1.x*sc, by = A1.y*sc, bz = A1.z*sc, bw = A1.w*sc;
            #pragma unroll
            for (int i = 0; i < 4; ++i){
                ax = fmaf(p[i], c0[i].x, ax); ay = fmaf(p[i], c0[i].y, ay);
                az = fmaf(p[i], c0[i].z, az); aw = fmaf(p[i], c0[i].w, aw);
                bx = fmaf(p[i], c1[i].x, bx); by = fmaf(p[i], c1[i].y, by);
                bz = fmaf(p[i], c1[i].z, bz); bw = fmaf(p[i], c1[i].w, bw);
            }
            A0 = make_float4(ax, ay, az, aw);
            A1 = make_float4(bx, by, bz, bw);
            m = m2;

            if (havenext){
                #pragma unroll
                for (int i = 0; i < 4; ++i){
                    li[i] = ni[i]; c0[i] = x0[i]; c1[i] = x1[i];
                }
            }
        }
    }
    if (tid == 0){
        g_m[b*SPL + sp] = m;
        g_z[b*SPL + sp] = Z;
    }
    float4* op = (float4*)(g_acc + (size_t)(b*SPL + sp)*NN + n0);
    op[0] = A0; op[1] = A1;
}

// ---------------------------------------------------------------------------
// Kernel 3: combine (R14 version). blocks 0..63: context c[b, n-quarter].
// blocks 64..191: attn + coverage, float4 flat-indexed; masked -> attn 0.
// ---------------------------------------------------------------------------
__global__ void k_combine(const float* __restrict__ cov,
                          float* __restrict__ out){
    int tid = threadIdx.x;
    if (blockIdx.x < 4*BB){
        int b = blockIdx.x >> 2, q = blockIdx.x & 3;
        __shared__ float sw[SPL];
        if (tid < 32){
            float mv = g_m[b*SPL + tid];
            float zv = g_z[b*SPL + tid];
            float M = mv;
            #pragma unroll
            for (int off = 16; off; off >>= 1)
                M = fmaxf(M, __shfl_xor_sync(0xffffffffu, M, off));
            float Zs = zv * __expf(mv - M);
            #pragma unroll
            for (int off = 16; off; off >>= 1)
                Zs += __shfl_xor_sync(0xffffffffu, Zs, off);
            float inv = 1.0f / Zs;
            sw[tid] = __expf(mv - M) * inv;
        }
        __syncthreads();
        if (tid < 128){
            int n0 = q*512 + tid*4;
            float4 r = make_float4(0.f,0.f,0.f,0.f);
            #pragma unroll
            for (int s = 0; s < SPL; ++s){
                float4 x = *(const float4*)(g_acc + (size_t)(b*SPL + s)*NN + n0);
                float wgt = sw[s];
                r.x = fmaf(wgt, x.x, r.x); r.y = fmaf(wgt, x.y, r.y);
                r.z = fmaf(wgt, x.z, r.z); r.w = fmaf(wgt, x.w, r.w);
            }
            *(float4*)(out + b*NN + n0) = r;
        }
    } else {
        __shared__ float sM[BB], sInv[BB];
        if (tid < BB){
            int b = tid;
            float M = -INFINITY;
            #pragma unroll
            for (int s = 0; s < SPL; ++s) M = fmaxf(M, g_m[b*SPL + s]);
            float Zs = 0.f;
            #pragma unroll
            for (int s = 0; s < SPL; ++s) Zs += g_z[b*SPL + s] * __expf(g_m[b*SPL + s] - M);
            sM[b] = M; sInv[b] = 1.0f / Zs;
        }
        __syncthreads();
        int q = (blockIdx.x - 4*BB) * 256 + tid;    // 128 blocks -> 8192 quads
        int flat = q * 4;
        if (q < (TT*BB)/4){
            float4 sc = *(const float4*)(g_scores + flat);
            float4 cv = *(const float4*)(cov + flat);
            uchar4 mk = *(const uchar4*)(g_mask8 + flat);
            int b0 = flat & (BB-1);
            float4 a;
            a.x = mk.x ? 0.f : __expf(sc.x - sM[b0  ]) * sInv[b0  ];
            a.y = mk.y ? 0.f : __expf(sc.y - sM[b0+1]) * sInv[b0+1];
            a.z = mk.z ? 0.f : __expf(sc.z - sM[b0+2]) * sInv[b0+2];
            a.w = mk.w ? 0.f : __expf(sc.w - sM[b0+3]) * sInv[b0+3];
            *(float4*)(out + BB*NN + flat) = a;
            float4 cg = make_float4(cv.x + a.x, cv.y + a.y, cv.z + a.z, cv.w + a.w);
            *(float4*)(out + BB*NN + TT*BB + flat) = cg;
        }
    }
}

// ---------------------------------------------------------------------------
extern "C" void kernel_launch(void* const* d_in, const int* in_sizes, int n_in,
                              void* d_out, int out_size){
    const float*         dec  = (const float*)d_in[0];          // [B,H]
    const float*         enc  = (const float*)d_in[1];          // [T,B,N]
    const unsigned char* mask = (const unsigned char*)d_in[2];  // [T,B] (dtype auto-detected)
    const float*         cov  = (const float*)d_in[3];          // [T,B]
    const float*         Wd   = (const float*)d_in[4];          // [N,H]
    const float*         bd   = (const float*)d_in[5];          // [N]
    const float*         wc   = (const float*)d_in[6];          // [N]
    const float*         v    = (const float*)d_in[7];          // [N]
    float* out = (float*)d_out;  // c[B,N] | attn[T,B] | coverage_out[T,B]

    k_decfea<<<512, 128>>>(dec, Wd, bd, mask);
    k_main<<<dim3(SPL, BB), THR>>>(enc, cov, wc, v);
    k_combine<<<4*BB + (TT*BB/4 + 255)/256, 256>>>(cov, out);
}